// round 3
// baseline (speedup 1.0000x reference)
#include <cuda_runtime.h>
#include <math.h>

#define NN 20000      // nodes
#define NE 320000     // edges
#define DM 256        // d_model
#define NH 8          // heads
#define DH 32         // head dim
#define DFF 512       // ffn hidden
#define NG 16         // graphs
#define NL 2          // layers

// ----------------------------- scratch (device globals, no allocs) ----------
__device__ float g_h  [NN * DM];
__device__ float g_q  [NN * DM];
__device__ float g_k  [NN * DM];
__device__ float g_v  [NN * DM];
__device__ float g_t  [NN * DM];
__device__ float g_ff [NN * DFF];
__device__ float g_msg[NN * DM];
__device__ float g_s  [NE * NH];
__device__ int   g_m  [NN * NH];   // float bits, atomicMax on int (all s > 0)
__device__ float g_den[NN * NH];
__device__ float g_gsum[NG * DM];
__device__ int   g_gcnt[NG];

// ----------------------------- embed ----------------------------------------
__global__ void embed_kernel(const float* __restrict__ feat, const float* __restrict__ lap,
                             const float* __restrict__ sign,
                             const float* __restrict__ Wh, const float* __restrict__ bh,
                             const float* __restrict__ Wlp, const float* __restrict__ blp,
                             float* __restrict__ h)
{
    int n = blockIdx.x;
    int d = threadIdx.x;
    __shared__ float sf[32];
    __shared__ float sl[16];
    if (d < 32) sf[d] = feat[n * 32 + d];
    else if (d < 48) sl[d - 32] = lap[n * 16 + (d - 32)] * sign[d - 32];
    __syncthreads();
    float acc = bh[d] + blp[d];
#pragma unroll
    for (int k = 0; k < 32; k++) acc += sf[k] * Wh[k * DM + d];
#pragma unroll
    for (int k = 0; k < 16; k++) acc += sl[k] * Wlp[k * DM + d];
    h[(size_t)n * DM + d] = acc;
}

// ----------------------------- SGEMM ----------------------------------------
// C[M,N] = A[M,K] @ B[K,N] (+bias) (+relu). 128x64 tile, BK=16, 256 threads, 8x4/thread.
#define BM 128
#define BN 64
#define BK 16
__global__ __launch_bounds__(256) void sgemm_kernel(
    const float* __restrict__ A, const float* __restrict__ B,
    const float* __restrict__ bias, float* __restrict__ C,
    int M, int Ncol, int K, int relu)
{
    __shared__ float As[BK][BM];
    __shared__ float Bs[BK][BN];
    int tid = threadIdx.x;
    int tcol = tid & 15;       // 0..15
    int trow = tid >> 4;       // 0..15
    int rowBase = blockIdx.y * BM;
    int colBase = blockIdx.x * BN;

    float acc[8][4];
#pragma unroll
    for (int i = 0; i < 8; i++)
#pragma unroll
        for (int j = 0; j < 4; j++) acc[i][j] = 0.f;

    for (int k0 = 0; k0 < K; k0 += BK) {
        // A tile: 128 rows x 16 k = 512 float4
#pragma unroll
        for (int t = 0; t < 2; t++) {
            int i = tid + t * 256;
            int ar = i >> 2;            // 0..127
            int ac = (i & 3) << 2;      // 0,4,8,12
            int grow = rowBase + ar;
            float4 v = make_float4(0.f, 0.f, 0.f, 0.f);
            if (grow < M)
                v = *reinterpret_cast<const float4*>(A + (size_t)grow * K + k0 + ac);
            As[ac + 0][ar] = v.x; As[ac + 1][ar] = v.y;
            As[ac + 2][ar] = v.z; As[ac + 3][ar] = v.w;
        }
        // B tile: 16 x 64 = 256 float4
        {
            int br = tid >> 4;          // 0..15
            int bc = (tid & 15) << 2;   // 0..60
            float4 v = *reinterpret_cast<const float4*>(B + (size_t)(k0 + br) * Ncol + colBase + bc);
            *reinterpret_cast<float4*>(&Bs[br][bc]) = v;
        }
        __syncthreads();
#pragma unroll
        for (int kk = 0; kk < BK; kk++) {
            float a[8], b[4];
#pragma unroll
            for (int i = 0; i < 8; i++) a[i] = As[kk][trow * 8 + i];
#pragma unroll
            for (int j = 0; j < 4; j++) b[j] = Bs[kk][tcol * 4 + j];
#pragma unroll
            for (int i = 0; i < 8; i++)
#pragma unroll
                for (int j = 0; j < 4; j++) acc[i][j] += a[i] * b[j];
        }
        __syncthreads();
    }

    int gcol = colBase + tcol * 4;
    float4 bv = make_float4(0.f, 0.f, 0.f, 0.f);
    if (bias) bv = *reinterpret_cast<const float4*>(bias + gcol);
#pragma unroll
    for (int i = 0; i < 8; i++) {
        int grow = rowBase + trow * 8 + i;
        if (grow >= M) continue;
        float4 o;
        o.x = acc[i][0] + bv.x; o.y = acc[i][1] + bv.y;
        o.z = acc[i][2] + bv.z; o.w = acc[i][3] + bv.w;
        if (relu) {
            o.x = fmaxf(o.x, 0.f); o.y = fmaxf(o.y, 0.f);
            o.z = fmaxf(o.z, 0.f); o.w = fmaxf(o.w, 0.f);
        }
        *reinterpret_cast<float4*>(C + (size_t)grow * Ncol + gcol) = o;
    }
}

// ----------------------------- edge kernels ---------------------------------
__global__ void zero_edge_scratch()
{
    int i = blockIdx.x * 256 + threadIdx.x;     // covers NN*256
    if (i < NN * NH) { g_m[i] = 0; g_den[i] = 0.f; }
    g_msg[i] = 0.f;
}

// warp per edge; lane covers dims [8*lane, 8*lane+8) -> head = lane>>2
__global__ __launch_bounds__(256) void edge_score_kernel(
    const float* __restrict__ Q, const float* __restrict__ K,
    const int* __restrict__ src, const int* __restrict__ dst)
{
    int e = blockIdx.x * 8 + (threadIdx.x >> 5);
    if (e >= NE) return;
    int lane = threadIdx.x & 31;
    int sn = src[e], dn = dst[e];
    const float4* kp = reinterpret_cast<const float4*>(K + (size_t)sn * DM + lane * 8);
    const float4* qp = reinterpret_cast<const float4*>(Q + (size_t)dn * DM + lane * 8);
    float4 k0 = kp[0], k1 = kp[1];
    float4 q0 = qp[0], q1 = qp[1];
    float dot = k0.x * q0.x + k0.y * q0.y + k0.z * q0.z + k0.w * q0.w
              + k1.x * q1.x + k1.y * q1.y + k1.z * q1.z + k1.w * q1.w;
    dot += __shfl_xor_sync(0xffffffffu, dot, 1);
    dot += __shfl_xor_sync(0xffffffffu, dot, 2);
    if ((lane & 3) == 0) {
        int head = lane >> 2;
        float sc = dot * 0.17677669529663687f;   // 1/sqrt(32)
        sc = fminf(fmaxf(sc, -5.f), 5.f);
        float s = expf(sc);                      // s in [e^-5, e^5], > 0
        g_s[(size_t)e * NH + head] = s;
        atomicMax(&g_m[(size_t)dn * NH + head], __float_as_int(s));
    }
}

__global__ __launch_bounds__(256) void edge_aggregate_kernel(
    const float* __restrict__ V,
    const int* __restrict__ src, const int* __restrict__ dst)
{
    int e = blockIdx.x * 8 + (threadIdx.x >> 5);
    if (e >= NE) return;
    int lane = threadIdx.x & 31;
    int sn = src[e], dn = dst[e];
    int head = lane >> 2;
    float s  = g_s[(size_t)e * NH + head];
    float mm = __int_as_float(g_m[(size_t)dn * NH + head]);
    float p  = expf(s - mm);
    if ((lane & 3) == 0) atomicAdd(&g_den[(size_t)dn * NH + head], p);
    const float4* vp = reinterpret_cast<const float4*>(V + (size_t)sn * DM + lane * 8);
    float4 v0 = vp[0], v1 = vp[1];
    float* mp = g_msg + (size_t)dn * DM + lane * 8;
    atomicAdd(mp + 0, p * v0.x); atomicAdd(mp + 1, p * v0.y);
    atomicAdd(mp + 2, p * v0.z); atomicAdd(mp + 3, p * v0.w);
    atomicAdd(mp + 4, p * v1.x); atomicAdd(mp + 5, p * v1.y);
    atomicAdd(mp + 6, p * v1.z); atomicAdd(mp + 7, p * v1.w);
}

__global__ void attn_norm_kernel()
{
    int n = blockIdx.x;
    int d = threadIdx.x;
    float dn = g_den[(size_t)n * NH + (d >> 5)];
    g_msg[(size_t)n * DM + d] /= (dn > 0.f ? dn : 1.f);
}

// ----------------------------- layernorm ------------------------------------
__device__ __forceinline__ float block_sum256(float v, float* red)
{
#pragma unroll
    for (int o = 16; o > 0; o >>= 1) v += __shfl_xor_sync(0xffffffffu, v, o);
    int w = threadIdx.x >> 5;
    if ((threadIdx.x & 31) == 0) red[w] = v;
    __syncthreads();
    if (threadIdx.x < 32) {
        float t = (threadIdx.x < 8) ? red[threadIdx.x] : 0.f;
#pragma unroll
        for (int o = 4; o > 0; o >>= 1) t += __shfl_xor_sync(0xffffffffu, t, o);
        if (threadIdx.x == 0) red[0] = t;
    }
    __syncthreads();
    float out = red[0];
    __syncthreads();
    return out;
}

__global__ void resid_ln_kernel(const float* __restrict__ xres, const float* __restrict__ y,
                                const float* __restrict__ bias,
                                const float* __restrict__ gamma, const float* __restrict__ beta,
                                float* __restrict__ out)
{
    __shared__ float red[32];
    int n = blockIdx.x, d = threadIdx.x;
    size_t idx = (size_t)n * DM + d;
    float x = xres[idx] + y[idx] + bias[d];
    float mean = block_sum256(x, red) * (1.f / DM);
    float dx = x - mean;
    float var = block_sum256(dx * dx, red) * (1.f / DM);
    out[idx] = gamma[d] * dx * rsqrtf(var + 1e-5f) + beta[d];
}

// ----------------------------- readout --------------------------------------
__global__ void zero_gsum_kernel()
{
    g_gsum[blockIdx.x * 256 + threadIdx.x] = 0.f;
}

__global__ void readout_kernel(const int* __restrict__ gid)
{
    int base = blockIdx.x * 32;
    int d = threadIdx.x;
    if (base >= NN) return;
    float acc = 0.f;
    int cg = gid[base];
    for (int i = 0; i < 32; i++) {
        int n = base + i;
        if (n >= NN) break;
        int g = gid[n];
        if (g != cg) {
            atomicAdd(&g_gsum[cg * DM + d], acc);
            acc = 0.f; cg = g;
        }
        acc += g_h[(size_t)n * DM + d];
    }
    atomicAdd(&g_gsum[cg * DM + d], acc);
}

__global__ void count_kernel(const int* __restrict__ gid)
{
    __shared__ int c[NG];
    if (threadIdx.x < NG) c[threadIdx.x] = 0;
    __syncthreads();
    for (int i = threadIdx.x; i < NN; i += blockDim.x)
        atomicAdd(&c[gid[i]], 1);
    __syncthreads();
    if (threadIdx.x < NG) g_gcnt[threadIdx.x] = c[threadIdx.x];
}

__global__ void final_kernel(float* __restrict__ out)
{
    int g = blockIdx.x, d = threadIdx.x;
    int c = g_gcnt[g];
    out[g * DM + d] = g_gsum[g * DM + d] / (float)(c > 0 ? c : 1);
}

// ----------------------------- host driver ----------------------------------
extern "C" void kernel_launch(void* const* d_in, const int* in_sizes, int n_in,
                              void* d_out, int out_size)
{
    const float* feat = (const float*)d_in[0];
    const float* lap  = (const float*)d_in[1];
    const float* sign = (const float*)d_in[2];
    const int*   src  = (const int*)  d_in[3];
    const int*   dst  = (const int*)  d_in[4];
    const int*   gid  = (const int*)  d_in[5];
    const float* Wh   = (const float*)d_in[6];
    const float* bh   = (const float*)d_in[7];
    const float* Wlp  = (const float*)d_in[8];
    const float* blp  = (const float*)d_in[9];
    const float* Wq   = (const float*)d_in[10];
    const float* Wk   = (const float*)d_in[11];
    const float* Wv   = (const float*)d_in[12];
    const float* Wo   = (const float*)d_in[13];
    const float* bo   = (const float*)d_in[14];
    const float* g1   = (const float*)d_in[15];
    const float* b1   = (const float*)d_in[16];
    const float* W1   = (const float*)d_in[17];
    const float* c1   = (const float*)d_in[18];
    const float* W2   = (const float*)d_in[19];
    const float* c2   = (const float*)d_in[20];
    const float* g2   = (const float*)d_in[21];
    const float* b2   = (const float*)d_in[22];
    float* out = (float*)d_out;

    float *h, *q, *k, *v, *t, *ff, *msg;
    cudaGetSymbolAddress((void**)&h,   g_h);
    cudaGetSymbolAddress((void**)&q,   g_q);
    cudaGetSymbolAddress((void**)&k,   g_k);
    cudaGetSymbolAddress((void**)&v,   g_v);
    cudaGetSymbolAddress((void**)&t,   g_t);
    cudaGetSymbolAddress((void**)&ff,  g_ff);
    cudaGetSymbolAddress((void**)&msg, g_msg);

    const int rowTiles = (NN + BM - 1) / BM;   // 157
    dim3 gemm256(DM / BN, rowTiles);           // (4, 157)
    dim3 gemm512(DFF / BN, rowTiles);          // (8, 157)

    embed_kernel<<<NN, 256>>>(feat, lap, sign, Wh, bh, Wlp, blp, h);

    for (int l = 0; l < NL; l++) {
        const float* wq = Wq + (size_t)l * DM * DM;
        const float* wk = Wk + (size_t)l * DM * DM;
        const float* wv = Wv + (size_t)l * DM * DM;
        const float* wo = Wo + (size_t)l * DM * DM;
        const float* w1 = W1 + (size_t)l * DM * DFF;
        const float* w2 = W2 + (size_t)l * DFF * DM;

        sgemm_kernel<<<gemm256, 256>>>(h, wq, nullptr, q, NN, DM, DM, 0);
        sgemm_kernel<<<gemm256, 256>>>(h, wk, nullptr, k, NN, DM, DM, 0);
        sgemm_kernel<<<gemm256, 256>>>(h, wv, nullptr, v, NN, DM, DM, 0);

        zero_edge_scratch<<<NN, 256>>>();
        edge_score_kernel<<<NE / 8, 256>>>(q, k, src, dst);
        edge_aggregate_kernel<<<NE / 8, 256>>>(v, src, dst);
        attn_norm_kernel<<<NN, 256>>>();

        sgemm_kernel<<<gemm256, 256>>>(msg, wo, nullptr, t, NN, DM, DM, 0);
        resid_ln_kernel<<<NN, 256>>>(h, t, bo + l * DM, g1 + l * DM, b1 + l * DM, h);

        sgemm_kernel<<<gemm512, 256>>>(h, w1, c1 + l * DFF, ff, NN, DFF, DM, 1);
        sgemm_kernel<<<gemm256, 256>>>(ff, w2, nullptr, t, NN, DM, DFF, 0);
        resid_ln_kernel<<<NN, 256>>>(h, t, c2 + l * DM, g2 + l * DM, b2 + l * DM, h);
    }

    zero_gsum_kernel<<<NG, 256>>>();
    readout_kernel<<<(NN + 31) / 32, 256>>>(gid);
    count_kernel<<<1, 256>>>(gid);
    final_kernel<<<NG, 256>>>(out);
}

// round 4
// speedup vs baseline: 1.0071x; 1.0071x over previous
#include <cuda_runtime.h>
#include <math.h>

#define NN 20000      // nodes
#define NE 320000     // edges
#define DM 256        // d_model
#define NH 8          // heads
#define DH 32         // head dim
#define DFF 512       // ffn hidden
#define NG 16         // graphs
#define NL 2          // layers

// ----------------------------- scratch (device globals, no allocs) ----------
__device__ float g_h  [NN * DM];
__device__ float g_q  [NN * DM];
__device__ float g_k  [NN * DM];
__device__ float g_v  [NN * DM];
__device__ float g_t  [NN * DM];
__device__ float g_ff [NN * DFF];
__device__ float g_msg[NN * DM];
__device__ float g_s  [NE * NH];
__device__ int   g_m  [NN * NH];   // float bits, atomicMax on int (all s > 0)
__device__ float g_den[NN * NH];
__device__ float g_gsum[NG * DM];
__device__ int   g_gcnt[NG];

// ----------------------------- embed ----------------------------------------
__global__ void embed_kernel(const float* __restrict__ feat, const float* __restrict__ lap,
                             const float* __restrict__ sign,
                             const float* __restrict__ Wh, const float* __restrict__ bh,
                             const float* __restrict__ Wlp, const float* __restrict__ blp,
                             float* __restrict__ h)
{
    int n = blockIdx.x;
    int d = threadIdx.x;
    __shared__ float sf[32];
    __shared__ float sl[16];
    if (d < 32) sf[d] = feat[n * 32 + d];
    else if (d < 48) sl[d - 32] = lap[n * 16 + (d - 32)] * sign[d - 32];
    __syncthreads();
    float acc = bh[d] + blp[d];
#pragma unroll
    for (int k = 0; k < 32; k++) acc += sf[k] * Wh[k * DM + d];
#pragma unroll
    for (int k = 0; k < 16; k++) acc += sl[k] * Wlp[k * DM + d];
    h[(size_t)n * DM + d] = acc;
}

// ----------------------------- SGEMM ----------------------------------------
// C[M,N] = A[M,K] @ B[K,N] (+bias) (+relu). 128x64 tile, BK=16, 256 threads, 8x4/thread.
#define BM 128
#define BN 64
#define BK 16
__global__ __launch_bounds__(256) void sgemm_kernel(
    const float* __restrict__ A, const float* __restrict__ B,
    const float* __restrict__ bias, float* __restrict__ C,
    int M, int Ncol, int K, int relu)
{
    __shared__ float As[BK][BM];
    __shared__ float Bs[BK][BN];
    int tid = threadIdx.x;
    int tcol = tid & 15;       // 0..15
    int trow = tid >> 4;       // 0..15
    int rowBase = blockIdx.y * BM;
    int colBase = blockIdx.x * BN;

    float acc[8][4];
#pragma unroll
    for (int i = 0; i < 8; i++)
#pragma unroll
        for (int j = 0; j < 4; j++) acc[i][j] = 0.f;

    for (int k0 = 0; k0 < K; k0 += BK) {
        // A tile: 128 rows x 16 k = 512 float4
#pragma unroll
        for (int t = 0; t < 2; t++) {
            int i = tid + t * 256;
            int ar = i >> 2;            // 0..127
            int ac = (i & 3) << 2;      // 0,4,8,12
            int grow = rowBase + ar;
            float4 v = make_float4(0.f, 0.f, 0.f, 0.f);
            if (grow < M)
                v = *reinterpret_cast<const float4*>(A + (size_t)grow * K + k0 + ac);
            As[ac + 0][ar] = v.x; As[ac + 1][ar] = v.y;
            As[ac + 2][ar] = v.z; As[ac + 3][ar] = v.w;
        }
        // B tile: 16 x 64 = 256 float4
        {
            int br = tid >> 4;          // 0..15
            int bc = (tid & 15) << 2;   // 0..60
            float4 v = *reinterpret_cast<const float4*>(B + (size_t)(k0 + br) * Ncol + colBase + bc);
            *reinterpret_cast<float4*>(&Bs[br][bc]) = v;
        }
        __syncthreads();
#pragma unroll
        for (int kk = 0; kk < BK; kk++) {
            float a[8], b[4];
#pragma unroll
            for (int i = 0; i < 8; i++) a[i] = As[kk][trow * 8 + i];
#pragma unroll
            for (int j = 0; j < 4; j++) b[j] = Bs[kk][tcol * 4 + j];
#pragma unroll
            for (int i = 0; i < 8; i++)
#pragma unroll
                for (int j = 0; j < 4; j++) acc[i][j] += a[i] * b[j];
        }
        __syncthreads();
    }

    int gcol = colBase + tcol * 4;
    float4 bv = make_float4(0.f, 0.f, 0.f, 0.f);
    if (bias) bv = *reinterpret_cast<const float4*>(bias + gcol);
#pragma unroll
    for (int i = 0; i < 8; i++) {
        int grow = rowBase + trow * 8 + i;
        if (grow >= M) continue;
        float4 o;
        o.x = acc[i][0] + bv.x; o.y = acc[i][1] + bv.y;
        o.z = acc[i][2] + bv.z; o.w = acc[i][3] + bv.w;
        if (relu) {
            o.x = fmaxf(o.x, 0.f); o.y = fmaxf(o.y, 0.f);
            o.z = fmaxf(o.z, 0.f); o.w = fmaxf(o.w, 0.f);
        }
        *reinterpret_cast<float4*>(C + (size_t)grow * Ncol + gcol) = o;
    }
}

// ----------------------------- edge kernels ---------------------------------
__global__ void zero_edge_scratch()
{
    int i = blockIdx.x * 256 + threadIdx.x;     // covers NN*256
    if (i < NN * NH) { g_m[i] = 0; g_den[i] = 0.f; }
    g_msg[i] = 0.f;
}

// warp per edge; lane covers dims [8*lane, 8*lane+8) -> head = lane>>2
__global__ __launch_bounds__(256) void edge_score_kernel(
    const float* __restrict__ Q, const float* __restrict__ K,
    const int* __restrict__ src, const int* __restrict__ dst)
{
    int e = blockIdx.x * 8 + (threadIdx.x >> 5);
    if (e >= NE) return;
    int lane = threadIdx.x & 31;
    int sn = src[e], dn = dst[e];
    const float4* kp = reinterpret_cast<const float4*>(K + (size_t)sn * DM + lane * 8);
    const float4* qp = reinterpret_cast<const float4*>(Q + (size_t)dn * DM + lane * 8);
    float4 k0 = kp[0], k1 = kp[1];
    float4 q0 = qp[0], q1 = qp[1];
    float dot = k0.x * q0.x + k0.y * q0.y + k0.z * q0.z + k0.w * q0.w
              + k1.x * q1.x + k1.y * q1.y + k1.z * q1.z + k1.w * q1.w;
    dot += __shfl_xor_sync(0xffffffffu, dot, 1);
    dot += __shfl_xor_sync(0xffffffffu, dot, 2);
    if ((lane & 3) == 0) {
        int head = lane >> 2;
        float sc = dot * 0.17677669529663687f;   // 1/sqrt(32)
        sc = fminf(fmaxf(sc, -5.f), 5.f);
        float s = expf(sc);                      // s in [e^-5, e^5], > 0
        g_s[(size_t)e * NH + head] = s;
        atomicMax(&g_m[(size_t)dn * NH + head], __float_as_int(s));
    }
}

__global__ __launch_bounds__(256) void edge_aggregate_kernel(
    const float* __restrict__ V,
    const int* __restrict__ src, const int* __restrict__ dst)
{
    int e = blockIdx.x * 8 + (threadIdx.x >> 5);
    if (e >= NE) return;
    int lane = threadIdx.x & 31;
    int sn = src[e], dn = dst[e];
    int head = lane >> 2;
    float s  = g_s[(size_t)e * NH + head];
    float mm = __int_as_float(g_m[(size_t)dn * NH + head]);
    float p  = expf(s - mm);
    if ((lane & 3) == 0) atomicAdd(&g_den[(size_t)dn * NH + head], p);
    const float4* vp = reinterpret_cast<const float4*>(V + (size_t)sn * DM + lane * 8);
    float4 v0 = vp[0], v1 = vp[1];
    float* mp = g_msg + (size_t)dn * DM + lane * 8;
    atomicAdd(mp + 0, p * v0.x); atomicAdd(mp + 1, p * v0.y);
    atomicAdd(mp + 2, p * v0.z); atomicAdd(mp + 3, p * v0.w);
    atomicAdd(mp + 4, p * v1.x); atomicAdd(mp + 5, p * v1.y);
    atomicAdd(mp + 6, p * v1.z); atomicAdd(mp + 7, p * v1.w);
}

__global__ void attn_norm_kernel()
{
    int n = blockIdx.x;
    int d = threadIdx.x;
    float dn = g_den[(size_t)n * NH + (d >> 5)];
    g_msg[(size_t)n * DM + d] /= (dn > 0.f ? dn : 1.f);
}

// ----------------------------- layernorm ------------------------------------
__device__ __forceinline__ float block_sum256(float v, float* red)
{
#pragma unroll
    for (int o = 16; o > 0; o >>= 1) v += __shfl_xor_sync(0xffffffffu, v, o);
    int w = threadIdx.x >> 5;
    if ((threadIdx.x & 31) == 0) red[w] = v;
    __syncthreads();
    if (threadIdx.x < 32) {
        float t = (threadIdx.x < 8) ? red[threadIdx.x] : 0.f;
#pragma unroll
        for (int o = 4; o > 0; o >>= 1) t += __shfl_xor_sync(0xffffffffu, t, o);
        if (threadIdx.x == 0) red[0] = t;
    }
    __syncthreads();
    float out = red[0];
    __syncthreads();
    return out;
}

__global__ void resid_ln_kernel(const float* __restrict__ xres, const float* __restrict__ y,
                                const float* __restrict__ bias,
                                const float* __restrict__ gamma, const float* __restrict__ beta,
                                float* __restrict__ out)
{
    __shared__ float red[32];
    int n = blockIdx.x, d = threadIdx.x;
    size_t idx = (size_t)n * DM + d;
    float x = xres[idx] + y[idx] + bias[d];
    float mean = block_sum256(x, red) * (1.f / DM);
    float dx = x - mean;
    float var = block_sum256(dx * dx, red) * (1.f / DM);
    out[idx] = gamma[d] * dx * rsqrtf(var + 1e-5f) + beta[d];
}

// ----------------------------- readout --------------------------------------
__global__ void zero_gsum_kernel()
{
    g_gsum[blockIdx.x * 256 + threadIdx.x] = 0.f;
}

__global__ void readout_kernel(const int* __restrict__ gid)
{
    int base = blockIdx.x * 32;
    int d = threadIdx.x;
    if (base >= NN) return;
    float acc = 0.f;
    int cg = gid[base];
    for (int i = 0; i < 32; i++) {
        int n = base + i;
        if (n >= NN) break;
        int g = gid[n];
        if (g != cg) {
            atomicAdd(&g_gsum[cg * DM + d], acc);
            acc = 0.f; cg = g;
        }
        acc += g_h[(size_t)n * DM + d];
    }
    atomicAdd(&g_gsum[cg * DM + d], acc);
}

__global__ void count_kernel(const int* __restrict__ gid)
{
    __shared__ int c[NG];
    if (threadIdx.x < NG) c[threadIdx.x] = 0;
    __syncthreads();
    for (int i = threadIdx.x; i < NN; i += blockDim.x)
        atomicAdd(&c[gid[i]], 1);
    __syncthreads();
    if (threadIdx.x < NG) g_gcnt[threadIdx.x] = c[threadIdx.x];
}

__global__ void final_kernel(float* __restrict__ out)
{
    int g = blockIdx.x, d = threadIdx.x;
    int c = g_gcnt[g];
    out[g * DM + d] = g_gsum[g * DM + d] / (float)(c > 0 ? c : 1);
}

// ----------------------------- host driver ----------------------------------
extern "C" void kernel_launch(void* const* d_in, const int* in_sizes, int n_in,
                              void* d_out, int out_size)
{
    const float* feat = (const float*)d_in[0];
    const float* lap  = (const float*)d_in[1];
    const float* sign = (const float*)d_in[2];
    const int*   src  = (const int*)  d_in[3];
    const int*   dst  = (const int*)  d_in[4];
    const int*   gid  = (const int*)  d_in[5];
    const float* Wh   = (const float*)d_in[6];
    const float* bh   = (const float*)d_in[7];
    const float* Wlp  = (const float*)d_in[8];
    const float* blp  = (const float*)d_in[9];
    const float* Wq   = (const float*)d_in[10];
    const float* Wk   = (const float*)d_in[11];
    const float* Wv   = (const float*)d_in[12];
    const float* Wo   = (const float*)d_in[13];
    const float* bo   = (const float*)d_in[14];
    const float* g1   = (const float*)d_in[15];
    const float* b1   = (const float*)d_in[16];
    const float* W1   = (const float*)d_in[17];
    const float* c1   = (const float*)d_in[18];
    const float* W2   = (const float*)d_in[19];
    const float* c2   = (const float*)d_in[20];
    const float* g2   = (const float*)d_in[21];
    const float* b2   = (const float*)d_in[22];
    float* out = (float*)d_out;

    float *h, *q, *k, *v, *t, *ff, *msg;
    cudaGetSymbolAddress((void**)&h,   g_h);
    cudaGetSymbolAddress((void**)&q,   g_q);
    cudaGetSymbolAddress((void**)&k,   g_k);
    cudaGetSymbolAddress((void**)&v,   g_v);
    cudaGetSymbolAddress((void**)&t,   g_t);
    cudaGetSymbolAddress((void**)&ff,  g_ff);
    cudaGetSymbolAddress((void**)&msg, g_msg);

    const int rowTiles = (NN + BM - 1) / BM;   // 157
    dim3 gemm256(DM / BN, rowTiles);           // (4, 157)
    dim3 gemm512(DFF / BN, rowTiles);          // (8, 157)

    embed_kernel<<<NN, 256>>>(feat, lap, sign, Wh, bh, Wlp, blp, h);

    for (int l = 0; l < NL; l++) {
        const float* wq = Wq + (size_t)l * DM * DM;
        const float* wk = Wk + (size_t)l * DM * DM;
        const float* wv = Wv + (size_t)l * DM * DM;
        const float* wo = Wo + (size_t)l * DM * DM;
        const float* w1 = W1 + (size_t)l * DM * DFF;
        const float* w2 = W2 + (size_t)l * DFF * DM;

        sgemm_kernel<<<gemm256, 256>>>(h, wq, nullptr, q, NN, DM, DM, 0);
        sgemm_kernel<<<gemm256, 256>>>(h, wk, nullptr, k, NN, DM, DM, 0);
        sgemm_kernel<<<gemm256, 256>>>(h, wv, nullptr, v, NN, DM, DM, 0);

        zero_edge_scratch<<<NN, 256>>>();
        edge_score_kernel<<<NE / 8, 256>>>(q, k, src, dst);
        edge_aggregate_kernel<<<NE / 8, 256>>>(v, src, dst);
        attn_norm_kernel<<<NN, 256>>>();

        sgemm_kernel<<<gemm256, 256>>>(msg, wo, nullptr, t, NN, DM, DM, 0);
        resid_ln_kernel<<<NN, 256>>>(h, t, bo + l * DM, g1 + l * DM, b1 + l * DM, h);

        sgemm_kernel<<<gemm512, 256>>>(h, w1, c1 + l * DFF, ff, NN, DFF, DM, 1);
        sgemm_kernel<<<gemm256, 256>>>(ff, w2, nullptr, t, NN, DM, DFF, 0);
        resid_ln_kernel<<<NN, 256>>>(h, t, c2 + l * DM, g2 + l * DM, b2 + l * DM, h);
    }

    zero_gsum_kernel<<<NG, 256>>>();
    readout_kernel<<<(NN + 31) / 32, 256>>>(gid);
    count_kernel<<<1, 256>>>(gid);
    final_kernel<<<NG, 256>>>(out);
}